// round 8
// baseline (speedup 1.0000x reference)
#include <cuda_runtime.h>
#include <math.h>
#include <stdint.h>

#define BB   32
#define TT   512
#define HH   256
#define CC   32
#define G4   1024   // 4*H
#define DD   256

typedef unsigned long long ull;

// ---------------- scratch (no allocations allowed) ----------------
// gx layout: [dir][t][b][col]  (col fastest, 1024 per dir)
__device__ float g_gx[(size_t)2 * TT * BB * G4];     // 134 MB
__device__ float g_hist[(size_t)2 * TT * HH * BB];   // [dir][t][n][b]  33 MB
__device__ float g_logits[(size_t)TT * BB * CC];     // [t][b][c]        2 MB

// ---------------- packed fp32x2 helpers ----------------
__device__ __forceinline__ ull ffma2(ull a, ull b, ull c) {
    ull d;
    asm("fma.rn.f32x2 %0, %1, %2, %3;" : "=l"(d) : "l"(a), "l"(b), "l"(c));
    return d;
}
__device__ __forceinline__ ull padd2(ull a, ull b) {
    ull d;
    asm("add.rn.f32x2 %0, %1, %2;" : "=l"(d) : "l"(a), "l"(b));
    return d;
}
__device__ __forceinline__ ull dup2(float x) {
    ull p = (ull)__float_as_uint(x);
    return p | (p << 32);
}
__device__ __forceinline__ float2 unp(ull v) {
    float2 f;
    asm("mov.b64 {%0, %1}, %2;" : "=f"(f.x), "=f"(f.y) : "l"(v));
    return f;
}

__device__ __forceinline__ float sigf(float x)  { return __fdividef(1.f, 1.f + __expf(-x)); }
__device__ __forceinline__ float tanhf_(float x){ return __fdividef(2.f, 1.f + __expf(-2.f * x)) - 1.f; }

// ---------------- cluster helpers ----------------
__device__ __forceinline__ uint32_t smem_u32(const void* p) {
    uint32_t a;
    asm("{ .reg .u64 t; cvta.to.shared.u64 t, %1; cvt.u32.u64 %0, t; }" : "=r"(a) : "l"(p));
    return a;
}
__device__ __forceinline__ void st_cluster_u64(uint32_t laddr, uint32_t rank, ull v) {
    asm volatile(
        "{ .reg .b32 ra; mapa.shared::cluster.u32 ra, %0, %1; "
        "st.shared::cluster.u64 [ra], %2; }"
        :: "r"(laddr), "r"(rank), "l"(v) : "memory");
}
#define CLUSTER_SYNC_() do { \
    asm volatile("barrier.cluster.arrive.aligned;" ::: "memory"); \
    asm volatile("barrier.cluster.wait.aligned;"   ::: "memory"); \
} while (0)

// ---------------- kernel A: embedding gather + x@Wi + bias (fp32x2) ----------------
// grid (512, 16): x = t, y = dir*8 + colblock(128 cols). 256 threads.
// smem: a_sm [256][32] floats (32KB, reused for transpose) + wd_sm [64][128] ull dup (64KB)
__global__ void __launch_bounds__(256) wi_gemm_kernel(
        const int* __restrict__ chars,
        const int* __restrict__ bigrams,
        const float* __restrict__ char_table,
        const float* __restrict__ bigram_table,
        const float* __restrict__ Wi_f,
        const float* __restrict__ bias_f,
        const float* __restrict__ Wi_b,
        const float* __restrict__ bias_b) {
    extern __shared__ float sm[];
    float* a_sm = sm;                       // 8192 floats = 32KB
    ull*   wd_sm = (ull*)(sm + 8192);       // 8192 ull = 64KB

    const int t   = blockIdx.x;
    const int yid = blockIdx.y;
    const int dir = yid >> 3;
    const int cb  = yid & 7;
    const float* Wi   = dir ? Wi_b  : Wi_f;
    const float* bias = dir ? bias_b : bias_f;

    const int tid = threadIdx.x;

    // ---- gather emb -> a_sm[k][b]  (lane = b -> conflict-free STS) ----
    {
        const int b    = tid & 31;
        const int part = tid >> 5;   // 0..7
        const int ci = chars[b * TT + t];
        const int bi = bigrams[b * TT + t];
        #pragma unroll
        for (int i = 0; i < 8; i++) {
            int k4 = part * 8 + i;   // 0..63
            float4 v;
            if (k4 < 32) v = ((const float4*)char_table)[(size_t)ci * 32 + k4];
            else         v = ((const float4*)bigram_table)[(size_t)bi * 32 + (k4 - 32)];
            a_sm[(k4 * 4 + 0) * 32 + b] = v.x;
            a_sm[(k4 * 4 + 1) * 32 + b] = v.y;
            a_sm[(k4 * 4 + 2) * 32 + b] = v.z;
            a_sm[(k4 * 4 + 3) * 32 + b] = v.w;
        }
    }

    // ---- GEMM mapping: thread = (4 cols, 4 batches) ----
    const int cg = tid >> 3;   // 0..31 : cols cg*4 .. cg*4+3
    const int bq = tid & 7;    // batches 4bq .. 4bq+3
    ull acc[8];
    #pragma unroll
    for (int i = 0; i < 8; i++) acc[i] = 0ull;

    const ulonglong2* a2 = (const ulonglong2*)a_sm;

    for (int ch = 0; ch < 4; ch++) {
        const int k0 = ch * 64;
        __syncthreads();
        for (int u = tid; u < 8192; u += 256) {
            int kk  = u >> 7;
            int col = u & 127;
            float wv = Wi[(size_t)(k0 + kk) * G4 + cb * 128 + col];
            wd_sm[u] = dup2(wv);
        }
        __syncthreads();
        #pragma unroll 8
        for (int kk = 0; kk < 64; kk++) {
            ulonglong2 hv = a2[(k0 + kk) * 8 + bq];   // 4 batches: (b0,b1),(b2,b3)
            const ull* wr = &wd_sm[kk * 128 + cg * 4];
            #pragma unroll
            for (int c = 0; c < 4; c++) {
                ull wd = wr[c];
                acc[2 * c]     = ffma2(hv.x, wd, acc[2 * c]);
                acc[2 * c + 1] = ffma2(hv.y, wd, acc[2 * c + 1]);
            }
        }
    }

    // ---- transpose in smem, then store as [dir][t][b][col] ----
    __syncthreads();
    {
        #pragma unroll
        for (int cc = 0; cc < 4; cc++) {
            int col = cg * 4 + cc;
            ull b2 = dup2(bias[cb * 128 + col]);
            float2 v01 = unp(padd2(acc[2 * cc],     b2));
            float2 v23 = unp(padd2(acc[2 * cc + 1], b2));
            a_sm[(bq * 4 + 0) * 129 + col] = v01.x;
            a_sm[(bq * 4 + 1) * 129 + col] = v01.y;
            a_sm[(bq * 4 + 2) * 129 + col] = v23.x;
            a_sm[(bq * 4 + 3) * 129 + col] = v23.y;
        }
    }
    __syncthreads();
    {
        float* outp = g_gx + (size_t)(dir * TT + t) * (32 * 1024) + cb * 128;
        #pragma unroll
        for (int i = 0; i < 4; i++) {
            int idx = tid + i * 256;      // 0..1023
            int b = idx >> 5, c4 = idx & 31;
            float4 v;
            v.x = a_sm[b * 129 + c4 * 4 + 0];
            v.y = a_sm[b * 129 + c4 * 4 + 1];
            v.z = a_sm[b * 129 + c4 * 4 + 2];
            v.w = a_sm[b * 129 + c4 * 4 + 3];
            *(float4*)(outp + (size_t)b * 1024 + c4 * 4) = v;
        }
    }
}

// ---------------- kernel B: recurrent scan, cluster version ----------------
// grid 128 CTAs of 128 threads; clusters of 8.
// cluster id = (dir, batch-group of 4), rank = col-group (32 h-cols).
// smem: Wh slice [256][128] f32 (128KB) | hd 2x[256][4] ull dup (16KB) | gates [128][4] f32 (2KB)
__global__ void __cluster_dims__(8, 1, 1) __launch_bounds__(128, 1)
scan_kernel(const float* __restrict__ Wh_f,
            const float* __restrict__ Wh_b,
            const int* __restrict__ seq_len) {
    extern __shared__ float sm[];
    float* sm_wh = sm;                      // 32768 floats
    ull*   sm_hd = (ull*)(sm + 32768);      // 2 * 1024 ull (double buffered)
    float* sm_g  = (float*)(sm_hd + 2048);  // 512 floats

    const int cidg = blockIdx.x >> 3;
    uint32_t rank;
    asm("mov.u32 %0, %%cluster_ctarank;" : "=r"(rank));
    const int dir = cidg >> 3;
    const int bg  = cidg & 7;
    const int cg  = (int)rank;
    const float* Wh = dir ? Wh_b : Wh_f;
    const int tid = threadIdx.x;

    // load Wh slice: sm_wh[k*128 + g*32 + m] = Wh[k][g*256 + cg*32 + m]
    {
        const float4* W4 = (const float4*)Wh;
        float4* d4 = (float4*)sm_wh;
        for (int u = tid; u < 8192; u += 128) {
            int k = u >> 5, l4 = u & 31;
            d4[u] = W4[(k * 1024 + (l4 >> 3) * 256 + cg * 32 + (l4 & 7) * 4) >> 2];
        }
    }
    // zero h buffer 0
    for (int u = tid; u < 1024; u += 128) sm_hd[u] = 0ull;

    // GEMM-phase mapping: thread = (col pair l0=2jp,l0+1) x (2 batches)
    const int jp = tid >> 1;                 // 0..63
    const int bh = tid & 1;                  // 0..1
    // combine-phase mapping
    const int m  = tid & 31;                 // h col within group
    const int bl = tid >> 5;                 // 0..3 local batch
    const int b_glob = bg * 4 + bl;
    const int sl = seq_len[b_glob];
    const int ncol = cg * 32 + m;            // global h col

    const int gq  = jp >> 4;                               // gate index of l0
    const int c0g = gq * 256 + cg * 32 + ((2 * jp) & 31);  // global gate col of l0
    const int b0  = bg * 4 + 2 * bh;

    float c_reg = 0.f, h_prev = 0.f;
    const uint32_t hd_u32 = smem_u32(sm_hd);

    // prefetch gx for first step
    int t0 = dir ? (TT - 1) : 0;
    size_t gidx = ((size_t)(dir * TT + t0) * 32 + b0) * 1024 + c0g;
    ull gx0 = *(const ull*)(g_gx + gidx);
    ull gx1 = *(const ull*)(g_gx + gidx + 1024);

    __syncthreads();
    CLUSTER_SYNC_();

    int cur = 0;
    for (int p = 0; p < TT; p++) {
        const int t = dir ? (TT - 1 - p) : p;

        // gates = gx + h @ Wh (packed fp32x2; w pairs raw, h duplicated)
        // buffer `cur` occupies ull [cur*1024, cur*1024+1024)
        const ulonglong2* hdc = (const ulonglong2*)(sm_hd + cur * 1024);
        ull a0 = gx0, a1 = gx1;
        #pragma unroll 8
        for (int k = 0; k < 256; k++) {
            ulonglong2 hv = hdc[k * 2 + bh];                 // {h_b0,h_b0},{h_b1,h_b1}
            ull wv = *(const ull*)&sm_wh[k * 128 + 2 * jp];  // {w_l0, w_l1}
            a0 = ffma2(wv, hv.x, a0);
            a1 = ffma2(wv, hv.y, a1);
        }

        // prefetch next step's gx while gates settle
        if (p < TT - 1) {
            int tn = dir ? (t - 1) : (t + 1);
            size_t gi = ((size_t)(dir * TT + tn) * 32 + b0) * 1024 + c0g;
            gx0 = *(const ull*)(g_gx + gi);
            gx1 = *(const ull*)(g_gx + gi + 1024);
        }

        // stage gates: sm_g[l*4 + b]
        {
            float2 f0 = unp(a0), f1 = unp(a1);
            int l0 = 2 * jp;
            sm_g[ l0      * 4 + 2 * bh    ] = f0.x;
            sm_g[(l0 + 1) * 4 + 2 * bh    ] = f0.y;
            sm_g[ l0      * 4 + 2 * bh + 1] = f1.x;
            sm_g[(l0 + 1) * 4 + 2 * bh + 1] = f1.y;
        }
        __syncthreads();

        // combine: thread = (h col m, batch bl)
        float gi_ = sm_g[( 0 + m) * 4 + bl];
        float gf_ = sm_g[(32 + m) * 4 + bl];
        float gc_ = sm_g[(64 + m) * 4 + bl];
        float go_ = sm_g[(96 + m) * 4 + bl];
        float c_new = sigf(gf_) * c_reg + sigf(gi_) * tanhf_(gc_);
        float h_new = sigf(go_) * tanhf_(c_new);
        bool  msk = (t < sl);
        if (msk) c_reg = c_new;
        float h_out = msk ? h_new : h_prev;
        h_prev = h_out;

        g_hist[((size_t)(dir * TT + t) * HH + ncol) * BB + b_glob] = h_out;

        // broadcast duplicated h to next buffer of all 8 cluster CTAs, then sync
        if (p < TT - 1) {
            ull hv = dup2(h_out);
            uint32_t off = hd_u32 + (uint32_t)((((cur ^ 1) * 1024) + ncol * 4 + bl) * 8);
            #pragma unroll
            for (int r = 0; r < 8; r++) st_cluster_u64(off, (uint32_t)r, hv);
            cur ^= 1;
            CLUSTER_SYNC_();   // also serves as the block barrier for sm_g reuse
        }
    }
}

// ---------------- kernel C: output projection + log_softmax ----------------
// grid 512 (t), 256 threads. smem: hsm[512][32] + lsm[32][33] + lse[32]  (~70KB -> 3 CTAs/SM)
__global__ void proj_kernel(const float* __restrict__ out_W,
                            const float* __restrict__ out_b) {
    extern __shared__ float sm[];
    float* hsm = sm;                       // 512*32
    float* lsm = sm + 512 * 32;            // 32*33
    float* lse = lsm + 32 * 33;            // 32

    const int t   = blockIdx.x;
    const int tid = threadIdx.x;

    float4* hd = (float4*)hsm;
    const float4* h0 = (const float4*)(g_hist + (size_t)t * HH * BB);
    const float4* h1 = (const float4*)(g_hist + (size_t)(TT + t) * HH * BB);
    #pragma unroll
    for (int i = 0; i < 16; i++) {
        int idx = tid + i * 256;           // 0..4095 float4
        hd[idx] = (idx < 2048) ? h0[idx] : h1[idx - 2048];
    }
    __syncthreads();

    const int b  = tid & 31;
    const int cg = tid >> 5;
    float acc[4];
    #pragma unroll
    for (int jj = 0; jj < 4; jj++) acc[jj] = out_b[cg * 4 + jj];
    #pragma unroll 8
    for (int k = 0; k < 512; k++) {
        float  hv = hsm[k * 32 + b];
        float4 ww = __ldg((const float4*)&out_W[k * CC + cg * 4]);  // warp-uniform, cached
        acc[0] += hv * ww.x; acc[1] += hv * ww.y; acc[2] += hv * ww.z; acc[3] += hv * ww.w;
    }
    #pragma unroll
    for (int jj = 0; jj < 4; jj++) lsm[b * 33 + cg * 4 + jj] = acc[jj];
    __syncthreads();

    if (tid < 32) {
        float mx = -1e30f;
        #pragma unroll
        for (int c = 0; c < 32; c++) mx = fmaxf(mx, lsm[tid * 33 + c]);
        float ssum = 0.f;
        #pragma unroll
        for (int c = 0; c < 32; c++) ssum += expf(lsm[tid * 33 + c] - mx);
        lse[tid] = mx + logf(ssum);
    }
    __syncthreads();

    float l = lse[b];
    #pragma unroll
    for (int jj = 0; jj < 4; jj++)
        g_logits[(size_t)t * BB * CC + b * CC + cg * 4 + jj] = acc[jj] - l;
}

// ---------------- kernel D: CRF normalizer + gold score ----------------
__global__ void crf_kernel(const int* __restrict__ seq_len,
                           const int* __restrict__ target,
                           const float* __restrict__ trans,
                           const float* __restrict__ start_trans,
                           const float* __restrict__ end_trans,
                           float* __restrict__ out) {
    const int b = blockIdx.x;
    const int j = threadIdx.x;
    const int sl = seq_len[b];

    float tr[32];
    #pragma unroll
    for (int i = 0; i < 32; i++) tr[i] = trans[i * 32 + j];

    float alpha = g_logits[(size_t)b * CC + j] + start_trans[j];

    for (int t = 1; t < sl; t++) {
        float emit = g_logits[(size_t)t * BB * CC + b * CC + j];
        float mx = -1e30f;
        #pragma unroll
        for (int i = 0; i < 32; i++) {
            float ai = __shfl_sync(0xffffffffu, alpha, i);
            mx = fmaxf(mx, ai + tr[i]);
        }
        float ssum = 0.f;
        #pragma unroll
        for (int i = 0; i < 32; i++) {
            float ai = __shfl_sync(0xffffffffu, alpha, i);
            ssum += __expf(ai + tr[i] - mx);
        }
        alpha = mx + __logf(ssum) + emit;
    }

    float v  = alpha + end_trans[j];
    float mx = v;
    #pragma unroll
    for (int o = 16; o > 0; o >>= 1) mx = fmaxf(mx, __shfl_xor_sync(0xffffffffu, mx, o));
    float se = __expf(v - mx);
    #pragma unroll
    for (int o = 16; o > 0; o >>= 1) se += __shfl_xor_sync(0xffffffffu, se, o);
    float norm = mx + logf(se);

    float gs = 0.f;
    for (int t = j; t < sl; t += 32) {
        int tg = target[b * TT + t];
        gs += g_logits[(size_t)t * BB * CC + b * CC + tg];
        if (t >= 1) gs += trans[target[b * TT + t - 1] * 32 + tg];
    }
    #pragma unroll
    for (int o = 16; o > 0; o >>= 1) gs += __shfl_xor_sync(0xffffffffu, gs, o);

    if (j == 0) {
        gs += start_trans[target[b * TT]] + end_trans[target[b * TT + sl - 1]];
        out[b] = norm - gs;
    }
}

// ---------------- launch ----------------
extern "C" void kernel_launch(void* const* d_in, const int* in_sizes, int n_in,
                              void* d_out, int out_size) {
    const int*   chars        = (const int*)d_in[0];
    const int*   bigrams      = (const int*)d_in[1];
    const int*   seq_len      = (const int*)d_in[2];
    const int*   target       = (const int*)d_in[3];
    const float* char_table   = (const float*)d_in[4];
    const float* bigram_table = (const float*)d_in[5];
    const float* Wi_f         = (const float*)d_in[6];
    const float* Wh_f         = (const float*)d_in[7];
    const float* b_f          = (const float*)d_in[8];
    const float* Wi_b         = (const float*)d_in[9];
    const float* Wh_b         = (const float*)d_in[10];
    const float* b_b          = (const float*)d_in[11];
    const float* out_W        = (const float*)d_in[12];
    const float* out_b        = (const float*)d_in[13];
    const float* trans        = (const float*)d_in[14];
    const float* start_trans  = (const float*)d_in[15];
    const float* end_trans    = (const float*)d_in[16];
    float* out = (float*)d_out;

    const int SMEM_A = 32768 + 65536;                              // 98304
    const int SMEM_S = 32768 * 4 + 2048 * 8 + 512 * 4;             // 149504
    const int SMEM_P = (512 * 32 + 32 * 33 + 32) * (int)sizeof(float);  // 69888

    cudaFuncSetAttribute(wi_gemm_kernel, cudaFuncAttributeMaxDynamicSharedMemorySize, SMEM_A);
    cudaFuncSetAttribute(scan_kernel,    cudaFuncAttributeMaxDynamicSharedMemorySize, SMEM_S);
    cudaFuncSetAttribute(proj_kernel,    cudaFuncAttributeMaxDynamicSharedMemorySize, SMEM_P);

    dim3 ga(TT, 16);
    wi_gemm_kernel<<<ga, 256, SMEM_A>>>(chars, bigrams, char_table, bigram_table,
                                        Wi_f, b_f, Wi_b, b_b);

    scan_kernel<<<128, 128, SMEM_S>>>(Wh_f, Wh_b, seq_len);

    proj_kernel<<<TT, 256, SMEM_P>>>(out_W, out_b);

    crf_kernel<<<BB, 32>>>(seq_len, target, trans, start_trans, end_trans, out);
}